// round 5
// baseline (speedup 1.0000x reference)
#include <cuda_runtime.h>
#include <cuda_bf16.h>
#include <math.h>

// Problem dims
#define Nn    128
#define Tt    32
#define TCAP  33
#define Dd    400
#define Ww    512
#define Hh    1024
#define Vv    10000
#define Gg    4096   // 4*H

typedef unsigned long long ull;

// ---------------- device scratch (static, allocation-guard compliant) ----------------
__device__ __align__(16) float g_A[Nn * 16 * Hh];              // A_flat [n][l][h], 8 MB
__device__ __align__(16) float g_h[Nn * Hh];                   // current hidden
__device__ __align__(16) float g_c[Nn * Hh];                   // current cell
__device__ __align__(16) float g_attnP[Nn * Gg];               // (attn @ Wattn), 2 MB
__device__ __align__(16) float g_xw[(size_t)Tt * Nn * Gg];     // x_t @ Wx, rows t*128+n, 64 MB
__device__ __align__(16) float g_P[(size_t)Nn * 16 * Gg];      // A_flat @ Wattn, rows n*16+l, 32 MB
__device__ __align__(16) float g_zs[2 * Nn * Gg];              // split-K partials of h@Wh, 4 MB
__device__ __align__(16) float g_hn[(size_t)Tt * Nn * Hh];     // hidden states, rows t*128+n, 16 MB
__device__ __align__(16) float g_scores[(size_t)Tt * Nn * Vv]; // 4096 x 10000 logits, 164 MB
__device__ __align__(16) float g_nll[Tt * Nn];

// ---------------- f32x2 / async helpers ----------------
__device__ __forceinline__ ull ffma2(ull a, ull b, ull c) {
    ull d;
    asm("fma.rn.f32x2 %0, %1, %2, %3;" : "=l"(d) : "l"(a), "l"(b), "l"(c));
    return d;
}
__device__ __forceinline__ void unpack2(ull v, float& x, float& y) {
    asm("mov.b64 {%0, %1}, %2;" : "=f"(x), "=f"(y) : "l"(v));
}
__device__ __forceinline__ void cpa8(unsigned dst, const float* src) {
    asm volatile("cp.async.ca.shared.global [%0], [%1], 8;" :: "r"(dst), "l"(src));
}
__device__ __forceinline__ void cpa_commit() {
    asm volatile("cp.async.commit_group;" ::: "memory");
}
__device__ __forceinline__ void cpa_wait0() {
    asm volatile("cp.async.wait_group 0;" ::: "memory");
}

// ---------------- 1) feature projection: A[n][l][h] = sum_d F[n][d][l]*Wp[d][h] + bp[h] ----------------
__global__ void proj_kernel(const float* __restrict__ features,
                            const float* __restrict__ W_proj,
                            const float* __restrict__ b_proj) {
    __shared__ float Fs[Dd * 16];
    int n  = blockIdx.y;
    int h0 = blockIdx.x * 128;
    int t  = threadIdx.x;

    const float* F = features + (size_t)n * Dd * 16;
    for (int i = t; i < Dd * 16; i += 256) Fs[i] = F[i];
    __syncthreads();

    int h  = h0 + (t & 127);
    int lb = (t >> 7) * 8;
    float acc[8];
    #pragma unroll
    for (int i = 0; i < 8; i++) acc[i] = 0.f;

    for (int d = 0; d < Dd; d++) {
        float w = W_proj[(size_t)d * Hh + h];
        #pragma unroll
        for (int i = 0; i < 8; i++) acc[i] += Fs[d * 16 + lb + i] * w;
    }
    float bp = b_proj[h];
    #pragma unroll
    for (int i = 0; i < 8; i++)
        g_A[(size_t)n * 16 * Hh + (lb + i) * Hh + h] = acc[i] + bp;
}

// ---------------- 2) h0 = mean over l; init h and c ----------------
__global__ void h0_kernel() {
    int idx = blockIdx.x * blockDim.x + threadIdx.x;
    if (idx >= Nn * Hh) return;
    int n = idx >> 10;
    float s = 0.f;
    #pragma unroll
    for (int l = 0; l < 16; l++) s += g_A[(size_t)n * 16 * Hh + l * Hh + (idx & (Hh - 1))];
    s *= (1.0f / 16.0f);
    g_h[idx] = s;
    g_c[idx] = s;
}

// ---------------- generic f32x2 GEMM body: C[M x N] = A[M x K] * B[K x N] ----------------
// Tile 128x64, BK=32, 256 threads, 8x4 micro-tile, k-pair f32x2 lanes.
// Double-buffered smem; A filled via cp.async (8B chunks ARE the k-pairs); B reg-prefetched.
// MODE 0: xw   A = embedding gather (K=512),  B=Wx,      C=g_xw
// MODE 1: P    A = g_A   (2048 rows, K=1024), B=Wattn,   C=g_P
// MODE 2: voc  A = g_hn  (4096 rows, K=1024), B=W_vocab, C=g_scores (+bias, col guard)
// MODE 3: hWh  A = g_h   (128 rows),  split-K=2 over K=1024 via 'by', C=g_zs
template<int MODE>
__device__ __forceinline__ void gemm_body(
    int bx, int by,
    const float* __restrict__ Bmat,
    const int*   __restrict__ captions,
    const float* __restrict__ W_embed,
    const float* __restrict__ bias,
    ull (*As2)[16][128], ull (*Bs2)[16][64])
{
    constexpr int KLEN  = (MODE == 0 || MODE == 3) ? 512 : 1024;
    constexpr int NITER = KLEN / 32;
    constexpr int LDB   = (MODE == 2) ? Vv : Gg;
    constexpr int LDC   = (MODE == 2) ? Vv : Gg;

    const int tid = threadIdx.x;
    const int tx  = tid & 15;      // col group: cols tx*4 + j
    const int ty  = tid >> 4;      // row group: rows ty*8 + i
    const int n0  = bx * 64;

    int m0, kbase;
    float* C;
    if (MODE == 3) {
        m0 = 0; kbase = by * 512;
        C = g_zs + (size_t)by * (Nn * Gg);
    } else {
        m0 = by * 128; kbase = 0;
        C = (MODE == 0) ? g_xw : ((MODE == 1) ? g_P : g_scores);
    }

    // A-fill: thread covers rows ar_base + 32p, k columns kc..kc+3 (two 8B k-pairs)
    const int ar_base = tid >> 3;          // 0..31
    const int kc      = (tid & 7) * 4;     // 0..28
    const float* aptr[4];
    #pragma unroll
    for (int p = 0; p < 4; p++) {
        int gr = m0 + ar_base + p * 32;
        const float* rowp;
        if (MODE == 0) {
            int tok = captions[(gr & 127) * TCAP + (gr >> 7)];
            rowp = W_embed + (size_t)tok * Ww;
        } else if (MODE == 1) {
            rowp = g_A + (size_t)gr * Hh;
        } else if (MODE == 2) {
            rowp = g_hn + (size_t)gr * Hh;
        } else {
            rowp = g_h + (size_t)gr * Hh;
        }
        aptr[p] = rowp + kbase + kc;
    }
    // smem byte addresses for this thread's two cp.async destinations per p
    const unsigned asBase = (unsigned)__cvta_generic_to_shared(&As2[0][0][0]);
    const unsigned aDst0  = asBase + (unsigned)(((kc >> 1) * 128 + ar_base) * 8);
    // buffer stride = 16*128*8 bytes; k2+1 stride = 128*8 bytes

    // B-fill: thread covers k-pair bk2 (rows 2bk2, 2bk2+1), cols cg4..cg4+3
    const int bk2 = tid >> 4;            // 0..15
    const int cg4 = (tid & 15) * 4;      // 0..60
    const float* bptr = Bmat + (size_t)(kbase + 2 * bk2) * LDB + n0 + cg4;
    const bool bok = (MODE != 2) || (n0 + cg4 + 3 < Vv);   // Vv is float4-granular

    float4 bA, bB;

    // ---- prologue: fill buffer 0 ----
    #pragma unroll
    for (int p = 0; p < 4; p++) {
        unsigned d = aDst0 + (unsigned)(p * 32 * 8);
        cpa8(d, aptr[p]);
        cpa8(d + 128 * 8, aptr[p] + 2);
        aptr[p] += 32;
    }
    cpa_commit();
    if (bok) {
        bA = *(const float4*)(bptr);
        bB = *(const float4*)(bptr + LDB);
    } else {
        bA = make_float4(0.f, 0.f, 0.f, 0.f);
        bB = bA;
    }
    bptr += (size_t)32 * LDB;
    *(float4*)&Bs2[0][bk2][cg4]     = make_float4(bA.x, bB.x, bA.y, bB.y);
    *(float4*)&Bs2[0][bk2][cg4 + 2] = make_float4(bA.z, bB.z, bA.w, bB.w);
    cpa_wait0();
    __syncthreads();

    ull acc[8][4];
    #pragma unroll
    for (int i = 0; i < 8; i++)
        #pragma unroll
        for (int j = 0; j < 4; j++) acc[i][j] = 0ULL;

    for (int it = 0; it < NITER; it++) {
        const int cur = it & 1;
        const int nxt = cur ^ 1;
        const bool more = (it + 1 < NITER);

        if (more) {
            // async A fill into nxt buffer
            unsigned bufOff = (unsigned)(nxt * 16 * 128 * 8);
            #pragma unroll
            for (int p = 0; p < 4; p++) {
                unsigned d = aDst0 + bufOff + (unsigned)(p * 32 * 8);
                cpa8(d, aptr[p]);
                cpa8(d + 128 * 8, aptr[p] + 2);
                aptr[p] += 32;
            }
            cpa_commit();
            // B prefetch into regs
            if (bok) {
                bA = *(const float4*)(bptr);
                bB = *(const float4*)(bptr + LDB);
            }
            bptr += (size_t)32 * LDB;
        }

        // ---- inner product over 16 k-pairs (vectorized fragment loads) ----
        #pragma unroll
        for (int k2 = 0; k2 < 16; k2++) {
            ull a[8], b[4];
            #pragma unroll
            for (int q = 0; q < 4; q++) {
                ulonglong2 v = *(const ulonglong2*)&As2[cur][k2][ty * 8 + 2 * q];
                a[2 * q] = v.x; a[2 * q + 1] = v.y;
            }
            #pragma unroll
            for (int q = 0; q < 2; q++) {
                ulonglong2 v = *(const ulonglong2*)&Bs2[cur][k2][tx * 4 + 2 * q];
                b[2 * q] = v.x; b[2 * q + 1] = v.y;
            }
            #pragma unroll
            for (int i = 0; i < 8; i++)
                #pragma unroll
                for (int j = 0; j < 4; j++)
                    acc[i][j] = ffma2(a[i], b[j], acc[i][j]);
        }

        if (more) {
            *(float4*)&Bs2[nxt][bk2][cg4]     = make_float4(bA.x, bB.x, bA.y, bB.y);
            *(float4*)&Bs2[nxt][bk2][cg4 + 2] = make_float4(bA.z, bB.z, bA.w, bB.w);
            cpa_wait0();
            __syncthreads();
        }
    }

    // ---- epilogue: fold lanes, bias, float4 store ----
    const int colb = n0 + tx * 4;
    const bool cok = (MODE != 2) || (colb + 3 < Vv);
    float4 bv = make_float4(0.f, 0.f, 0.f, 0.f);
    if (MODE == 2 && cok) bv = *(const float4*)&bias[colb];

    #pragma unroll
    for (int i = 0; i < 8; i++) {
        if (cok) {
            int row = m0 + ty * 8 + i;
            float lo, hi;
            float4 r;
            unpack2(acc[i][0], lo, hi); r.x = lo + hi;
            unpack2(acc[i][1], lo, hi); r.y = lo + hi;
            unpack2(acc[i][2], lo, hi); r.z = lo + hi;
            unpack2(acc[i][3], lo, hi); r.w = lo + hi;
            if (MODE == 2) { r.x += bv.x; r.y += bv.y; r.z += bv.z; r.w += bv.w; }
            *(float4*)&C[(size_t)row * LDC + colb] = r;
        }
    }
}

template<int MODE>
__global__ void __launch_bounds__(256, 2) gemm_f32x2(
    const float* __restrict__ Bmat,
    const int*   __restrict__ captions,
    const float* __restrict__ W_embed,
    const float* __restrict__ bias)
{
    __shared__ ull As2[2][16][128];
    __shared__ ull Bs2[2][16][64];
    gemm_body<MODE>(blockIdx.x, blockIdx.y, Bmat, captions, W_embed, bias, As2, Bs2);
}

// ---------------- attention body: w = softmax(h.A/sqrt(H)); attnP = sum_l w_l P[n,l,:] ----------------
// 256 threads; ph aliases 4KB of caller smem, scbuf 32 floats.
__device__ __forceinline__ void attn_body(int n, float* ph, float* scbuf) {
    float* sc  = scbuf;
    float* wsm = scbuf + 16;
    int t = threadIdx.x;

    #pragma unroll
    for (int i = 0; i < 4; i++) ph[t + 256 * i] = g_h[(size_t)n * Hh + t + 256 * i];
    __syncthreads();

    int warp = t >> 5, lane = t & 31;
    #pragma unroll
    for (int li = 0; li < 2; li++) {
        int l = warp + 8 * li;
        const float* Arow = g_A + (size_t)n * 16 * Hh + (size_t)l * Hh;
        float s = 0.f;
        for (int h = lane; h < Hh; h += 32) s += ph[h] * Arow[h];
        #pragma unroll
        for (int o = 16; o > 0; o >>= 1) s += __shfl_xor_sync(0xffffffff, s, o);
        if (lane == 0) sc[l] = s;
    }
    __syncthreads();

    if (t < 32) {
        float v = (t < 16) ? sc[t] * 0.03125f : -1e30f;   // 1/sqrt(1024)
        float m = v;
        #pragma unroll
        for (int o = 16; o > 0; o >>= 1) m = fmaxf(m, __shfl_xor_sync(0xffffffff, m, o));
        float e = (t < 16) ? expf(v - m) : 0.f;
        float se = e;
        #pragma unroll
        for (int o = 16; o > 0; o >>= 1) se += __shfl_xor_sync(0xffffffff, se, o);
        if (t < 16) wsm[t] = e / se;
    }
    __syncthreads();

    const float* Pn = g_P + (size_t)n * 16 * Gg;
    float w0 = wsm[0], w1 = wsm[1], w2 = wsm[2], w3 = wsm[3];
    float w4 = wsm[4], w5 = wsm[5], w6 = wsm[6], w7 = wsm[7];
    float w8 = wsm[8], w9 = wsm[9], wa = wsm[10], wb = wsm[11];
    float wc = wsm[12], wd = wsm[13], we = wsm[14], wf = wsm[15];
    for (int c = t; c < Gg; c += 256) {
        float a = w0 * Pn[c]           + w1 * Pn[c + Gg]       + w2 * Pn[c + 2 * Gg]  + w3 * Pn[c + 3 * Gg]
                + w4 * Pn[c + 4 * Gg]  + w5 * Pn[c + 5 * Gg]   + w6 * Pn[c + 6 * Gg]  + w7 * Pn[c + 7 * Gg]
                + w8 * Pn[c + 8 * Gg]  + w9 * Pn[c + 9 * Gg]   + wa * Pn[c + 10 * Gg] + wb * Pn[c + 11 * Gg]
                + wc * Pn[c + 12 * Gg] + wd * Pn[c + 13 * Gg]  + we * Pn[c + 14 * Gg] + wf * Pn[c + 15 * Gg];
        g_attnP[(size_t)n * Gg + c] = a;
    }
}

// ---------------- fused per-step kernel: blocks 0..127 = h@Wh GEMM (split-K=2), 128..255 = attn ----------------
__global__ void __launch_bounds__(256, 2) step_kernel(const float* __restrict__ Wh) {
    __shared__ ull As2[2][16][128];
    __shared__ ull Bs2[2][16][64];
    if (blockIdx.x < 128) {
        gemm_body<3>(blockIdx.x & 63, blockIdx.x >> 6, Wh, nullptr, nullptr, nullptr, As2, Bs2);
    } else {
        attn_body(blockIdx.x - 128, (float*)&As2[0][0][0], (float*)&Bs2[0][0][0]);
    }
}

// ---------------- gates: z = z0+z1+xw+attnP+b; LSTM update; store h into hn[t] ----------------
__device__ __forceinline__ float4 f4add5(float4 a, float4 b, float4 c, float4 d, float4 e) {
    return make_float4(a.x + b.x + c.x + d.x + e.x,
                       a.y + b.y + c.y + d.y + e.y,
                       a.z + b.z + c.z + d.z + e.z,
                       a.w + b.w + c.w + d.w + e.w);
}
__device__ __forceinline__ void lstm1(float zi, float zf, float zo, float zg,
                                      float cin, float& cout, float& hout) {
    float si = 1.f / (1.f + expf(-zi));
    float sf = 1.f / (1.f + expf(-zf));
    float so = 1.f / (1.f + expf(-zo));
    float gg = tanhf(zg);
    cout = sf * cin + si * gg;
    hout = so * tanhf(cout);
}

__global__ void gates_kernel(const float* __restrict__ b, int t) {
    int q = blockIdx.x * blockDim.x + threadIdx.x;     // handles 4 h-elements
    if (q >= (Nn * Hh) / 4) return;
    int idx = q * 4;                  // n*H + h
    int n  = idx >> 10;
    int h4 = (idx & (Hh - 1)) >> 2;   // float4 index within gate row

    const float4* z0 = (const float4*)(g_zs + (size_t)n * Gg);
    const float4* z1 = (const float4*)(g_zs + (size_t)(Nn + n) * Gg);
    const float4* xw = (const float4*)(g_xw + ((size_t)t * Nn + n) * Gg);
    const float4* ap = (const float4*)(g_attnP + (size_t)n * Gg);
    const float4* b4 = (const float4*)b;

    float4 zi = f4add5(z0[h4],       z1[h4],       xw[h4],       ap[h4],       b4[h4]);
    float4 zf = f4add5(z0[h4 + 256], z1[h4 + 256], xw[h4 + 256], ap[h4 + 256], b4[h4 + 256]);
    float4 zo = f4add5(z0[h4 + 512], z1[h4 + 512], xw[h4 + 512], ap[h4 + 512], b4[h4 + 512]);
    float4 zg = f4add5(z0[h4 + 768], z1[h4 + 768], xw[h4 + 768], ap[h4 + 768], b4[h4 + 768]);

    float4 cin = ((const float4*)g_c)[q];
    float4 co, ho;
    lstm1(zi.x, zf.x, zo.x, zg.x, cin.x, co.x, ho.x);
    lstm1(zi.y, zf.y, zo.y, zg.y, cin.y, co.y, ho.y);
    lstm1(zi.z, zf.z, zo.z, zg.z, cin.z, co.z, ho.z);
    lstm1(zi.w, zf.w, zo.w, zg.w, cin.w, co.w, ho.w);

    ((float4*)g_c)[q] = co;
    ((float4*)g_h)[q] = ho;
    ((float4*)(g_hn + (size_t)t * Nn * Hh))[q] = ho;
}

// ---------------- per-row log-softmax NLL (masked) ----------------
__global__ void loss_kernel(const int* __restrict__ captions) {
    int r = blockIdx.x;            // r = t*128 + n
    int t = r >> 7, n = r & 127;
    int target = captions[n * TCAP + t + 1];
    const float* s = g_scores + (size_t)r * Vv;
    __shared__ float red[256];
    int tid = threadIdx.x;

    // Vv = 10000 = 2500 float4s
    const float4* s4 = (const float4*)s;
    float m = -1e30f;
    for (int v = tid; v < 2500; v += 256) {
        float4 q = s4[v];
        m = fmaxf(m, fmaxf(fmaxf(q.x, q.y), fmaxf(q.z, q.w)));
    }
    red[tid] = m; __syncthreads();
    for (int o = 128; o > 0; o >>= 1) {
        if (tid < o) red[tid] = fmaxf(red[tid], red[tid + o]);
        __syncthreads();
    }
    float mx = red[0];
    __syncthreads();

    float se = 0.f;
    for (int v = tid; v < 2500; v += 256) {
        float4 q = s4[v];
        se += expf(q.x - mx) + expf(q.y - mx) + expf(q.z - mx) + expf(q.w - mx);
    }
    red[tid] = se; __syncthreads();
    for (int o = 128; o > 0; o >>= 1) {
        if (tid < o) red[tid] += red[tid + o];
        __syncthreads();
    }
    if (tid == 0) {
        float lse = logf(red[0]) + mx;
        float nll = lse - s[target];
        g_nll[r] = (target != 0) ? nll : 0.f;
    }
}

// ---------------- deterministic final reduction ----------------
__global__ void finalize_kernel(float* out) {
    __shared__ float red[256];
    int tid = threadIdx.x;
    float s = 0.f;
    for (int i = tid; i < Tt * Nn; i += 256) s += g_nll[i];
    red[tid] = s; __syncthreads();
    for (int o = 128; o > 0; o >>= 1) {
        if (tid < o) red[tid] += red[tid + o];
        __syncthreads();
    }
    if (tid == 0) out[0] = red[0] * (1.0f / (float)Nn);
}

// ---------------- launch ----------------
extern "C" void kernel_launch(void* const* d_in, const int* in_sizes, int n_in,
                              void* d_out, int out_size) {
    const float* features = (const float*)d_in[0];
    const int*   captions = (const int*)  d_in[1];
    const float* W_embed  = (const float*)d_in[2];
    const float* W_proj   = (const float*)d_in[3];
    const float* b_proj   = (const float*)d_in[4];
    const float* Wx       = (const float*)d_in[5];
    const float* Wh       = (const float*)d_in[6];
    const float* Wattn    = (const float*)d_in[7];
    const float* b        = (const float*)d_in[8];
    const float* W_vocab  = (const float*)d_in[9];
    const float* b_vocab  = (const float*)d_in[10];
    float* out = (float*)d_out;

    proj_kernel<<<dim3(8, 128), 256>>>(features, W_proj, b_proj);
    h0_kernel<<<512, 256>>>();

    // precompute x@Wx for all steps (rows t*128+n) and P = A_flat@Wattn (rows n*16+l)
    gemm_f32x2<0><<<dim3(64, 32), 256>>>(Wx,    captions, W_embed, nullptr);
    gemm_f32x2<1><<<dim3(64, 16), 256>>>(Wattn, captions, W_embed, nullptr);

    for (int t = 0; t < Tt; t++) {
        step_kernel<<<256, 256>>>(Wh);          // attn + h@Wh (split-K=2), concurrent block roles
        gates_kernel<<<128, 256>>>(b, t);
    }

    gemm_f32x2<2><<<dim3(157, 32), 256>>>(W_vocab, captions, W_embed, b_vocab);
    loss_kernel<<<Tt * Nn, 256>>>(captions);
    finalize_kernel<<<1, 256>>>(out);
}

// round 8
// speedup vs baseline: 1.1067x; 1.1067x over previous
#include <cuda_runtime.h>
#include <cuda_bf16.h>
#include <math.h>

// Problem dims
#define Nn    128
#define Tt    32
#define TCAP  33
#define Dd    400
#define Ww    512
#define Hh    1024
#define Vv    10000
#define Gg    4096   // 4*H

typedef unsigned long long ull;

// ---------------- device scratch (static, allocation-guard compliant) ----------------
__device__ __align__(16) float g_A[Nn * 16 * Hh];              // A_flat [n][l][h], 8 MB
__device__ __align__(16) float g_h[Nn * Hh];                   // current hidden
__device__ __align__(16) float g_c[Nn * Hh];                   // current cell
__device__ __align__(16) float g_attnP[Nn * Gg];               // (attn @ Wattn), 2 MB
__device__ __align__(16) float g_xw[(size_t)Tt * Nn * Gg];     // x_t @ Wx, rows t*128+n, 64 MB
__device__ __align__(16) float g_P[(size_t)Nn * 16 * Gg];      // A_flat @ Wattn, rows n*16+l, 32 MB
__device__ __align__(16) float g_zs[2 * Nn * Gg];              // split-K partials of h@Wh, 4 MB
__device__ __align__(16) float g_hn[(size_t)Tt * Nn * Hh];     // hidden states, rows t*128+n, 16 MB
__device__ __align__(16) float g_scores[(size_t)Tt * Nn * Vv]; // 4096 x 10000 logits, 164 MB
__device__ __align__(16) float g_nll[Tt * Nn];

// ---------------- f32x2 / async helpers ----------------
__device__ __forceinline__ ull ffma2(ull a, ull b, ull c) {
    ull d;
    asm("fma.rn.f32x2 %0, %1, %2, %3;" : "=l"(d) : "l"(a), "l"(b), "l"(c));
    return d;
}
__device__ __forceinline__ void unpack2(ull v, float& x, float& y) {
    asm("mov.b64 {%0, %1}, %2;" : "=f"(x), "=f"(y) : "l"(v));
}
__device__ __forceinline__ void cpa16(unsigned dst, const float* src) {
    asm volatile("cp.async.cg.shared.global [%0], [%1], 16;" :: "r"(dst), "l"(src));
}
__device__ __forceinline__ void cpa_commit() {
    asm volatile("cp.async.commit_group;" ::: "memory");
}
__device__ __forceinline__ void cpa_wait0() {
    asm volatile("cp.async.wait_group 0;" ::: "memory");
}

// ---------------- 1) feature projection: A[n][l][h] = sum_d F[n][d][l]*Wp[d][h] + bp[h] ----------------
__global__ void proj_kernel(const float* __restrict__ features,
                            const float* __restrict__ W_proj,
                            const float* __restrict__ b_proj) {
    __shared__ float Fs[Dd * 16];
    int n  = blockIdx.y;
    int h0 = blockIdx.x * 128;
    int t  = threadIdx.x;

    const float* F = features + (size_t)n * Dd * 16;
    for (int i = t; i < Dd * 16; i += 256) Fs[i] = F[i];
    __syncthreads();

    int h  = h0 + (t & 127);
    int lb = (t >> 7) * 8;
    float acc[8];
    #pragma unroll
    for (int i = 0; i < 8; i++) acc[i] = 0.f;

    for (int d = 0; d < Dd; d++) {
        float w = W_proj[(size_t)d * Hh + h];
        #pragma unroll
        for (int i = 0; i < 8; i++) acc[i] += Fs[d * 16 + lb + i] * w;
    }
    float bp = b_proj[h];
    #pragma unroll
    for (int i = 0; i < 8; i++)
        g_A[(size_t)n * 16 * Hh + (lb + i) * Hh + h] = acc[i] + bp;
}

// ---------------- 2) h0 = mean over l; init h and c ----------------
__global__ void h0_kernel() {
    int idx = blockIdx.x * blockDim.x + threadIdx.x;
    if (idx >= Nn * Hh) return;
    int n = idx >> 10;
    float s = 0.f;
    #pragma unroll
    for (int l = 0; l < 16; l++) s += g_A[(size_t)n * 16 * Hh + l * Hh + (idx & (Hh - 1))];
    s *= (1.0f / 16.0f);
    g_h[idx] = s;
    g_c[idx] = s;
}

// ---------------- generic f32x2 GEMM body: C[M x N] = A[M x K] * B[K x N] ----------------
// Tile 128x64, BK=32, 256 threads, 8x4 micro-tile, k-pair f32x2 lanes.
// A: double-buffered smem in k-quad layout, filled by 16B cp.async (chunk == element).
// B: single-buffered smem, register-prefetched (R4-proven path).
// MODE 0: xw   A = embedding gather (K=512),  B=Wx,      C=g_xw
// MODE 1: P    A = g_A   (2048 rows, K=1024), B=Wattn,   C=g_P
// MODE 2: voc  A = g_hn  (4096 rows, K=1024), B=W_vocab, C=g_scores (+bias, col guard)
// MODE 3: hWh  A = g_h   (128 rows),  split-K=2 over K=1024 via 'by', C=g_zs
template<int MODE>
__device__ __forceinline__ void gemm_body(
    int bx, int by,
    const float* __restrict__ Bmat,
    const int*   __restrict__ captions,
    const float* __restrict__ W_embed,
    const float* __restrict__ bias,
    ulonglong2 (*As4)[8][129], ull (*Bs2)[66])
{
    constexpr int KLEN  = (MODE == 0 || MODE == 3) ? 512 : 1024;
    constexpr int NITER = KLEN / 32;
    constexpr int LDB   = (MODE == 2) ? Vv : Gg;
    constexpr int LDC   = (MODE == 2) ? Vv : Gg;

    const int tid = threadIdx.x;
    const int tx  = tid & 15;      // col group: cols tx + 16*j
    const int ty  = tid >> 4;      // row group: rows ty*8 + i
    const int n0  = bx * 64;

    int m0, kbase;
    float* C;
    if (MODE == 3) {
        m0 = 0; kbase = by * 512;
        C = g_zs + (size_t)by * (Nn * Gg);
    } else {
        m0 = by * 128; kbase = 0;
        C = (MODE == 0) ? g_xw : ((MODE == 1) ? g_P : g_scores);
    }

    // A-fill: thread covers rows ar_base + 32p, local k = 4*k4 .. 4*k4+3 (one 16B chunk)
    const int ar_base = tid >> 3;          // 0..31
    const int k4      = tid & 7;           // 0..7
    const float* aptr[4];
    #pragma unroll
    for (int p = 0; p < 4; p++) {
        int gr = m0 + ar_base + p * 32;
        const float* rowp;
        if (MODE == 0) {
            int tok = captions[(gr & 127) * TCAP + (gr >> 7)];
            rowp = W_embed + (size_t)tok * Ww;
        } else if (MODE == 1) {
            rowp = g_A + (size_t)gr * Hh;
        } else if (MODE == 2) {
            rowp = g_hn + (size_t)gr * Hh;
        } else {
            rowp = g_h + (size_t)gr * Hh;
        }
        aptr[p] = rowp + kbase + 4 * k4;
    }
    const unsigned asBase = (unsigned)__cvta_generic_to_shared(&As4[0][0][0]);
    const unsigned aDst0  = asBase + (unsigned)((k4 * 129 + ar_base) * 16);
    constexpr unsigned ABUF = 8u * 129u * 16u;   // 16512 bytes per buffer

    // B-fill: thread covers k-pair bk2 (rows 2bk2, 2bk2+1), cols cg4..cg4+3
    const int bk2 = tid >> 4;            // 0..15
    const int cg4 = (tid & 15) * 4;      // 0..60
    const float* bptr = Bmat + (size_t)(kbase + 2 * bk2) * LDB + n0 + cg4;
    const bool bok = (MODE != 2) || (n0 + cg4 + 3 < Vv);   // Vv % 4 == 0 -> exact

    float4 bA = make_float4(0.f, 0.f, 0.f, 0.f);
    float4 bB = bA;

    // ---- prologue: cp.async A into buffer 0; B via regs ----
    #pragma unroll
    for (int p = 0; p < 4; p++) {
        cpa16(aDst0 + (unsigned)(p * 32 * 16), aptr[p]);
        aptr[p] += 32;
    }
    cpa_commit();
    if (bok) {
        bA = *(const float4*)(bptr);
        bB = *(const float4*)(bptr + LDB);
    }
    bptr += (size_t)32 * LDB;
    *(float4*)&Bs2[bk2][cg4]     = make_float4(bA.x, bB.x, bA.y, bB.y);
    *(float4*)&Bs2[bk2][cg4 + 2] = make_float4(bA.z, bB.z, bA.w, bB.w);
    cpa_wait0();
    __syncthreads();

    ull acc[8][4];
    #pragma unroll
    for (int i = 0; i < 8; i++)
        #pragma unroll
        for (int j = 0; j < 4; j++) acc[i][j] = 0ULL;

    for (int it = 0; it < NITER; it++) {
        const int cur = it & 1;
        const bool more = (it + 1 < NITER);

        if (more) {
            const unsigned bufOff = (cur ^ 1) * ABUF;
            #pragma unroll
            for (int p = 0; p < 4; p++) {
                cpa16(aDst0 + bufOff + (unsigned)(p * 32 * 16), aptr[p]);
                aptr[p] += 32;
            }
            cpa_commit();
            if (bok) {
                bA = *(const float4*)(bptr);
                bB = *(const float4*)(bptr + LDB);
            }
            bptr += (size_t)32 * LDB;
        }

        // ---- inner product: 8 k-quads (= 16 k-pairs) ----
        const ulonglong2 (*Ac)[129] = As4[cur];
        #pragma unroll
        for (int kq = 0; kq < 8; kq++) {
            ull b0[4], b1[4];
            #pragma unroll
            for (int j = 0; j < 4; j++) {
                b0[j] = Bs2[2 * kq][tx + 16 * j];
                b1[j] = Bs2[2 * kq + 1][tx + 16 * j];
            }
            #pragma unroll
            for (int half = 0; half < 2; half++) {
                ulonglong2 av[4];
                #pragma unroll
                for (int q = 0; q < 4; q++) av[q] = Ac[kq][ty * 8 + half * 4 + q];
                #pragma unroll
                for (int q = 0; q < 4; q++) {
                    const int i = half * 4 + q;
                    #pragma unroll
                    for (int j = 0; j < 4; j++) {
                        acc[i][j] = ffma2(av[q].x, b0[j], acc[i][j]);
                        acc[i][j] = ffma2(av[q].y, b1[j], acc[i][j]);
                    }
                }
            }
        }
        __syncthreads();   // all reads of Bs2 done

        if (more) {
            *(float4*)&Bs2[bk2][cg4]     = make_float4(bA.x, bB.x, bA.y, bB.y);
            *(float4*)&Bs2[bk2][cg4 + 2] = make_float4(bA.z, bB.z, bA.w, bB.w);
            cpa_wait0();
            __syncthreads();
        }
    }

    // ---- epilogue: fold lanes, bias, store (R4-proven scalar path) ----
    #pragma unroll
    for (int i = 0; i < 8; i++) {
        int row = m0 + ty * 8 + i;
        float* crow = C + (size_t)row * LDC;
        #pragma unroll
        for (int j = 0; j < 4; j++) {
            int col = n0 + tx + 16 * j;
            if (MODE != 2 || col < Vv) {
                float lo, hi;
                unpack2(acc[i][j], lo, hi);
                float v = lo + hi;
                if (MODE == 2) v += bias[col];
                crow[col] = v;
            }
        }
    }
}

template<int MODE>
__global__ void __launch_bounds__(256, 2) gemm_f32x2(
    const float* __restrict__ Bmat,
    const int*   __restrict__ captions,
    const float* __restrict__ W_embed,
    const float* __restrict__ bias)
{
    __shared__ ulonglong2 As4[2][8][129];
    __shared__ ull Bs2[16][66];
    gemm_body<MODE>(blockIdx.x, blockIdx.y, Bmat, captions, W_embed, bias, As4, Bs2);
}

// ---------------- attention body: w = softmax(h.A/sqrt(H)); attnP = sum_l w_l P[n,l,:] ----------------
// 256 threads; ph aliases 4KB of caller smem, scbuf 32 floats.
__device__ __forceinline__ void attn_body(int n, float* ph, float* scbuf) {
    float* sc  = scbuf;
    float* wsm = scbuf + 16;
    int t = threadIdx.x;

    #pragma unroll
    for (int i = 0; i < 4; i++) ph[t + 256 * i] = g_h[(size_t)n * Hh + t + 256 * i];
    __syncthreads();

    int warp = t >> 5, lane = t & 31;
    #pragma unroll
    for (int li = 0; li < 2; li++) {
        int l = warp + 8 * li;
        const float* Arow = g_A + (size_t)n * 16 * Hh + (size_t)l * Hh;
        float s = 0.f;
        for (int h = lane; h < Hh; h += 32) s += ph[h] * Arow[h];
        #pragma unroll
        for (int o = 16; o > 0; o >>= 1) s += __shfl_xor_sync(0xffffffff, s, o);
        if (lane == 0) sc[l] = s;
    }
    __syncthreads();

    if (t < 32) {
        float v = (t < 16) ? sc[t] * 0.03125f : -1e30f;   // 1/sqrt(1024)
        float m = v;
        #pragma unroll
        for (int o = 16; o > 0; o >>= 1) m = fmaxf(m, __shfl_xor_sync(0xffffffff, m, o));
        float e = (t < 16) ? expf(v - m) : 0.f;
        float se = e;
        #pragma unroll
        for (int o = 16; o > 0; o >>= 1) se += __shfl_xor_sync(0xffffffff, se, o);
        if (t < 16) wsm[t] = e / se;
    }
    __syncthreads();

    const float* Pn = g_P + (size_t)n * 16 * Gg;
    float w0 = wsm[0], w1 = wsm[1], w2 = wsm[2], w3 = wsm[3];
    float w4 = wsm[4], w5 = wsm[5], w6 = wsm[6], w7 = wsm[7];
    float w8 = wsm[8], w9 = wsm[9], wa = wsm[10], wb = wsm[11];
    float wc = wsm[12], wd = wsm[13], we = wsm[14], wf = wsm[15];
    for (int c = t; c < Gg; c += 256) {
        float a = w0 * Pn[c]           + w1 * Pn[c + Gg]       + w2 * Pn[c + 2 * Gg]  + w3 * Pn[c + 3 * Gg]
                + w4 * Pn[c + 4 * Gg]  + w5 * Pn[c + 5 * Gg]   + w6 * Pn[c + 6 * Gg]  + w7 * Pn[c + 7 * Gg]
                + w8 * Pn[c + 8 * Gg]  + w9 * Pn[c + 9 * Gg]   + wa * Pn[c + 10 * Gg] + wb * Pn[c + 11 * Gg]
                + wc * Pn[c + 12 * Gg] + wd * Pn[c + 13 * Gg]  + we * Pn[c + 14 * Gg] + wf * Pn[c + 15 * Gg];
        g_attnP[(size_t)n * Gg + c] = a;
    }
}

// ---------------- fused per-step kernel: blocks 0..127 = h@Wh GEMM (split-K=2), 128..255 = attn ----------------
__global__ void __launch_bounds__(256, 2) step_kernel(const float* __restrict__ Wh) {
    __shared__ ulonglong2 As4[2][8][129];
    __shared__ ull Bs2[16][66];
    if (blockIdx.x < 128) {
        gemm_body<3>(blockIdx.x & 63, blockIdx.x >> 6, Wh, nullptr, nullptr, nullptr, As4, Bs2);
    } else {
        attn_body(blockIdx.x - 128, (float*)&As4[0][0][0], (float*)&Bs2[0][0]);
    }
}

// ---------------- gates: z = z0+z1+xw+attnP+b; LSTM update; store h into hn[t] ----------------
__device__ __forceinline__ float4 f4add5(float4 a, float4 b, float4 c, float4 d, float4 e) {
    return make_float4(a.x + b.x + c.x + d.x + e.x,
                       a.y + b.y + c.y + d.y + e.y,
                       a.z + b.z + c.z + d.z + e.z,
                       a.w + b.w + c.w + d.w + e.w);
}
__device__ __forceinline__ void lstm1(float zi, float zf, float zo, float zg,
                                      float cin, float& cout, float& hout) {
    float si = 1.f / (1.f + expf(-zi));
    float sf = 1.f / (1.f + expf(-zf));
    float so = 1.f / (1.f + expf(-zo));
    float gg = tanhf(zg);
    cout = sf * cin + si * gg;
    hout = so * tanhf(cout);
}

__global__ void gates_kernel(const float* __restrict__ b, int t) {
    int q = blockIdx.x * blockDim.x + threadIdx.x;     // handles 4 h-elements
    if (q >= (Nn * Hh) / 4) return;
    int idx = q * 4;                  // n*H + h
    int n  = idx >> 10;
    int h4 = (idx & (Hh - 1)) >> 2;   // float4 index within gate row

    const float4* z0 = (const float4*)(g_zs + (size_t)n * Gg);
    const float4* z1 = (const float4*)(g_zs + (size_t)(Nn + n) * Gg);
    const float4* xw = (const float4*)(g_xw + ((size_t)t * Nn + n) * Gg);
    const float4* ap = (const float4*)(g_attnP + (size_t)n * Gg);
    const float4* b4 = (const float4*)b;

    float4 zi = f4add5(z0[h4],       z1[h4],       xw[h4],       ap[h4],       b4[h4]);
    float4 zf = f4add5(z0[h4 + 256], z1[h4 + 256], xw[h4 + 256], ap[h4 + 256], b4[h4 + 256]);
    float4 zo = f4add5(z0[h4 + 512], z1[h4 + 512], xw[h4 + 512], ap[h4 + 512], b4[h4 + 512]);
    float4 zg = f4add5(z0[h4 + 768], z1[h4 + 768], xw[h4 + 768], ap[h4 + 768], b4[h4 + 768]);

    float4 cin = ((const float4*)g_c)[q];
    float4 co, ho;
    lstm1(zi.x, zf.x, zo.x, zg.x, cin.x, co.x, ho.x);
    lstm1(zi.y, zf.y, zo.y, zg.y, cin.y, co.y, ho.y);
    lstm1(zi.z, zf.z, zo.z, zg.z, cin.z, co.z, ho.z);
    lstm1(zi.w, zf.w, zo.w, zg.w, cin.w, co.w, ho.w);

    ((float4*)g_c)[q] = co;
    ((float4*)g_h)[q] = ho;
    ((float4*)(g_hn + (size_t)t * Nn * Hh))[q] = ho;
}

// ---------------- per-row log-softmax NLL (masked) ----------------
__global__ void loss_kernel(const int* __restrict__ captions) {
    int r = blockIdx.x;            // r = t*128 + n
    int t = r >> 7, n = r & 127;
    int target = captions[n * TCAP + t + 1];
    const float* s = g_scores + (size_t)r * Vv;
    __shared__ float red[256];
    int tid = threadIdx.x;

    // Vv = 10000 = 2500 float4s
    const float4* s4 = (const float4*)s;
    float m = -1e30f;
    for (int v = tid; v < 2500; v += 256) {
        float4 q = s4[v];
        m = fmaxf(m, fmaxf(fmaxf(q.x, q.y), fmaxf(q.z, q.w)));
    }
    red[tid] = m; __syncthreads();
    for (int o = 128; o > 0; o >>= 1) {
        if (tid < o) red[tid] = fmaxf(red[tid], red[tid + o]);
        __syncthreads();
    }
    float mx = red[0];
    __syncthreads();

    float se = 0.f;
    for (int v = tid; v < 2500; v += 256) {
        float4 q = s4[v];
        se += expf(q.x - mx) + expf(q.y - mx) + expf(q.z - mx) + expf(q.w - mx);
    }
    red[tid] = se; __syncthreads();
    for (int o = 128; o > 0; o >>= 1) {
        if (tid < o) red[tid] += red[tid + o];
        __syncthreads();
    }
    if (tid == 0) {
        float lse = logf(red[0]) + mx;
        float nll = lse - s[target];
        g_nll[r] = (target != 0) ? nll : 0.f;
    }
}

// ---------------- deterministic final reduction ----------------
__global__ void finalize_kernel(float* out) {
    __shared__ float red[256];
    int tid = threadIdx.x;
    float s = 0.f;
    for (int i = tid; i < Tt * Nn; i += 256) s += g_nll[i];
    red[tid] = s; __syncthreads();
    for (int o = 128; o > 0; o >>= 1) {
        if (tid < o) red[tid] += red[tid + o];
        __syncthreads();
    }
    if (tid == 0) out[0] = red[0] * (1.0f / (float)Nn);
}

// ---------------- launch ----------------
extern "C" void kernel_launch(void* const* d_in, const int* in_sizes, int n_in,
                              void* d_out, int out_size) {
    const float* features = (const float*)d_in[0];
    const int*   captions = (const int*)  d_in[1];
    const float* W_embed  = (const float*)d_in[2];
    const float* W_proj   = (const float*)d_in[3];
    const float* b_proj   = (const float*)d_in[4];
    const float* Wx       = (const float*)d_in[5];
    const float* Wh       = (const float*)d_in[6];
    const float* Wattn    = (const float*)d_in[7];
    const float* b        = (const float*)d_in[8];
    const float* W_vocab  = (const float*)d_in[9];
    const float* b_vocab  = (const float*)d_in[10];
    float* out = (float*)d_out;

    proj_kernel<<<dim3(8, 128), 256>>>(features, W_proj, b_proj);
    h0_kernel<<<512, 256>>>();

    // precompute x@Wx for all steps (rows t*128+n) and P = A_flat@Wattn (rows n*16+l)
    gemm_f32x2<0><<<dim3(64, 32), 256>>>(Wx,    captions, W_embed, nullptr);
    gemm_f32x2<1><<<dim3(64, 16), 256>>>(Wattn, captions, W_embed, nullptr);

    for (int t = 0; t < Tt; t++) {
        step_kernel<<<256, 256>>>(Wh);          // attn + h@Wh (split-K=2), concurrent block roles
        gates_kernel<<<128, 256>>>(b, t);
    }

    gemm_f32x2<2><<<dim3(157, 32), 256>>>(W_vocab, captions, W_embed, b_vocab);
    loss_kernel<<<Tt * Nn, 256>>>(captions);
    finalize_kernel<<<1, 256>>>(out);
}

// round 11
// speedup vs baseline: 2.2574x; 2.0399x over previous
#include <cuda_runtime.h>
#include <cuda_bf16.h>
#include <math.h>

// Problem dims
#define Nn    128
#define Tt    32
#define TCAP  33
#define Dd    400
#define Ww    512
#define Hh    1024
#define Vv    10000
#define Gg    4096   // 4*H

// ---------------- device scratch (static, allocation-guard compliant) ----------------
__device__ __align__(16) float g_A[Nn * 16 * Hh];              // A_flat [n][l][h], 8 MB
__device__ __align__(16) float g_h[Nn * Hh];                   // current hidden
__device__ __align__(16) float g_c[Nn * Hh];                   // current cell
__device__ __align__(16) float g_attnP[Nn * Gg];               // (attn @ Wattn), 2 MB
__device__ __align__(16) float g_xw[(size_t)Tt * Nn * Gg];     // x_t @ Wx, rows t*128+n, 64 MB
__device__ __align__(16) float g_P[(size_t)Nn * 16 * Gg];      // A_flat @ Wattn, rows n*16+l, 32 MB
__device__ __align__(16) float g_zs[2 * Nn * Gg];              // split-K partials of h@Wh, 4 MB
__device__ __align__(16) float g_hn[(size_t)Tt * Nn * Hh];     // hidden states, rows t*128+n, 16 MB
__device__ __align__(16) float g_scores[(size_t)Tt * Nn * Vv]; // 4096 x 10000 logits, 164 MB
__device__ __align__(16) float g_nll[Tt * Nn];

// ---------------- helpers ----------------
__device__ __forceinline__ unsigned tf32cvt(float f) {
    unsigned u;
    asm("cvt.rna.tf32.f32 %0, %1;" : "=r"(u) : "f"(f));
    return u;
}
__device__ __forceinline__ void mma_tf32(float* c, const unsigned* a, const unsigned* b) {
    asm("mma.sync.aligned.m16n8k8.row.col.f32.tf32.tf32.f32 "
        "{%0,%1,%2,%3}, {%4,%5,%6,%7}, {%8,%9}, {%0,%1,%2,%3};"
        : "+f"(c[0]), "+f"(c[1]), "+f"(c[2]), "+f"(c[3])
        : "r"(a[0]), "r"(a[1]), "r"(a[2]), "r"(a[3]), "r"(b[0]), "r"(b[1]));
}
__device__ __forceinline__ uint4 tf32x4(float4 v) {
    uint4 q;
    q.x = tf32cvt(v.x); q.y = tf32cvt(v.y); q.z = tf32cvt(v.z); q.w = tf32cvt(v.w);
    return q;
}

// ---------------- 1) feature projection: A[n][l][h] = sum_d F[n][d][l]*Wp[d][h] + bp[h] ----------------
__global__ void proj_kernel(const float* __restrict__ features,
                            const float* __restrict__ W_proj,
                            const float* __restrict__ b_proj) {
    __shared__ float Fs[Dd * 16];
    int n  = blockIdx.y;
    int h0 = blockIdx.x * 128;
    int t  = threadIdx.x;

    const float* F = features + (size_t)n * Dd * 16;
    for (int i = t; i < Dd * 16; i += 256) Fs[i] = F[i];
    __syncthreads();

    int h  = h0 + (t & 127);
    int lb = (t >> 7) * 8;
    float acc[8];
    #pragma unroll
    for (int i = 0; i < 8; i++) acc[i] = 0.f;

    for (int d = 0; d < Dd; d++) {
        float w = W_proj[(size_t)d * Hh + h];
        #pragma unroll
        for (int i = 0; i < 8; i++) acc[i] += Fs[d * 16 + lb + i] * w;
    }
    float bp = b_proj[h];
    #pragma unroll
    for (int i = 0; i < 8; i++)
        g_A[(size_t)n * 16 * Hh + (lb + i) * Hh + h] = acc[i] + bp;
}

// ---------------- 2) h0 = mean over l; init h and c ----------------
__global__ void h0_kernel() {
    int idx = blockIdx.x * blockDim.x + threadIdx.x;
    if (idx >= Nn * Hh) return;
    int n = idx >> 10;
    float s = 0.f;
    #pragma unroll
    for (int l = 0; l < 16; l++) s += g_A[(size_t)n * 16 * Hh + l * Hh + (idx & (Hh - 1))];
    s *= (1.0f / 16.0f);
    g_h[idx] = s;
    g_c[idx] = s;
}

// ---------------- TF32 tensor-core GEMM body: C[M x N] = A[M x K] * B[K x N] ----------------
// Tile 128x64, BK=32, 256 threads (8 warps as 4M x 2N -> warp tile 32x32).
// mma.sync m16n8k8 tf32. A/B register-prefetched (R4-proven), single smem buffer, 2 syncs/tile.
// MODE 0: xw   A = embedding gather (K=512),  B=Wx,      C=g_xw
// MODE 1: P    A = g_A   (2048 rows, K=1024), B=Wattn,   C=g_P
// MODE 2: voc  A = g_hn  (4096 rows, K=1024), B=W_vocab, C=g_scores (+bias, col guard)
// MODE 3: hWh  A = g_h   (128 rows),  split-K=2 over K=1024 via 'by', C=g_zs
template<int MODE>
__device__ __forceinline__ void gemm_body(
    int bx, int by,
    const float* __restrict__ Bmat,
    const int*   __restrict__ captions,
    const float* __restrict__ W_embed,
    const float* __restrict__ bias,
    unsigned (*As)[36], unsigned (*Bs)[72])
{
    constexpr int KLEN  = (MODE == 0 || MODE == 3) ? 512 : 1024;
    constexpr int NITER = KLEN / 32;
    constexpr int LDB   = (MODE == 2) ? Vv : Gg;
    constexpr int LDC   = (MODE == 2) ? Vv : Gg;

    const int tid  = threadIdx.x;
    const int lane = tid & 31;
    const int warp = tid >> 5;
    const int wm   = (warp >> 1) * 32;     // warp M offset within tile
    const int wn   = (warp & 1) * 32;      // warp N offset within tile
    const int gid  = lane >> 2;            // 0..7
    const int tig  = lane & 3;             // 0..3
    const int n0   = bx * 64;

    int m0, kbase;
    float* C;
    if (MODE == 3) {
        m0 = 0; kbase = by * 512;
        C = g_zs + (size_t)by * (Nn * Gg);
    } else {
        m0 = by * 128; kbase = 0;
        C = (MODE == 0) ? g_xw : ((MODE == 1) ? g_P : g_scores);
    }

    // ---- A fill: thread owns row lm, 16 consecutive k at offset lkk ----
    const int lm  = tid >> 1;              // 0..127
    const int lkk = (tid & 1) * 16;        // 0 or 16
    const float* aptr;
    {
        int gr = m0 + lm;
        const float* rowp;
        if (MODE == 0) {
            int tok = captions[(gr & 127) * TCAP + (gr >> 7)];
            rowp = W_embed + (size_t)tok * Ww;
        } else if (MODE == 1) {
            rowp = g_A + (size_t)gr * Hh;
        } else if (MODE == 2) {
            rowp = g_hn + (size_t)gr * Hh;
        } else {
            rowp = g_h + (size_t)gr * Hh;
        }
        aptr = rowp + kbase + lkk;
    }

    // ---- B fill: thread owns k-row bk, 8 consecutive cols at bj ----
    const int bk = tid >> 3;               // 0..31
    const int bj = (tid & 7) * 8;          // 0..56
    const float* bptr = Bmat + (size_t)(kbase + bk) * LDB + n0 + bj;
    const bool bok = (MODE != 2) || (n0 + bj < Vv);   // Vv % 8 == 0 -> chunk all-or-nothing

    // ---- initial gmem prefetch into regs ----
    float4 av0, av1, av2, av3, bu0, bu1;
    av0 = *(const float4*)(aptr);     av1 = *(const float4*)(aptr + 4);
    av2 = *(const float4*)(aptr + 8); av3 = *(const float4*)(aptr + 12);
    aptr += 32;
    if (bok) { bu0 = *(const float4*)(bptr); bu1 = *(const float4*)(bptr + 4); }
    else     { bu0 = make_float4(0.f,0.f,0.f,0.f); bu1 = bu0; }
    bptr += (size_t)32 * LDB;

    float acc[2][4][4];
    #pragma unroll
    for (int mt = 0; mt < 2; mt++)
        #pragma unroll
        for (int nt = 0; nt < 4; nt++)
            #pragma unroll
            for (int q = 0; q < 4; q++) acc[mt][nt][q] = 0.f;

    for (int it = 0; it < NITER; it++) {
        // ---- store prefetched tile to smem (tf32-rounded) ----
        *(uint4*)&As[lm][lkk + 0]  = tf32x4(av0);
        *(uint4*)&As[lm][lkk + 4]  = tf32x4(av1);
        *(uint4*)&As[lm][lkk + 8]  = tf32x4(av2);
        *(uint4*)&As[lm][lkk + 12] = tf32x4(av3);
        *(uint4*)&Bs[bk][bj]     = tf32x4(bu0);
        *(uint4*)&Bs[bk][bj + 4] = tf32x4(bu1);
        __syncthreads();

        // ---- prefetch next tile (latency overlaps compute) ----
        if (it + 1 < NITER) {
            av0 = *(const float4*)(aptr);     av1 = *(const float4*)(aptr + 4);
            av2 = *(const float4*)(aptr + 8); av3 = *(const float4*)(aptr + 12);
            aptr += 32;
            if (bok) { bu0 = *(const float4*)(bptr); bu1 = *(const float4*)(bptr + 4); }
            bptr += (size_t)32 * LDB;
        }

        // ---- compute: 4 k8 steps ----
        #pragma unroll
        for (int k8 = 0; k8 < 4; k8++) {
            const int kk = k8 * 8;
            unsigned afr[2][4];
            #pragma unroll
            for (int mt = 0; mt < 2; mt++) {
                int r = wm + mt * 16 + gid;
                afr[mt][0] = As[r][kk + tig];
                afr[mt][1] = As[r + 8][kk + tig];
                afr[mt][2] = As[r][kk + tig + 4];
                afr[mt][3] = As[r + 8][kk + tig + 4];
            }
            unsigned bfr[4][2];
            #pragma unroll
            for (int nt = 0; nt < 4; nt++) {
                int ccol = wn + nt * 8 + gid;
                bfr[nt][0] = Bs[kk + tig][ccol];
                bfr[nt][1] = Bs[kk + tig + 4][ccol];
            }
            #pragma unroll
            for (int mt = 0; mt < 2; mt++)
                #pragma unroll
                for (int nt = 0; nt < 4; nt++)
                    mma_tf32(acc[mt][nt], afr[mt], bfr[nt]);
        }
        __syncthreads();
    }

    // ---- epilogue: c-frag layout -> gmem (float2 stores; col even, Vv even) ----
    #pragma unroll
    for (int mt = 0; mt < 2; mt++) {
        #pragma unroll
        for (int nt = 0; nt < 4; nt++) {
            int col = n0 + wn + nt * 8 + 2 * tig;
            if (MODE != 2 || col < Vv) {
                float b0 = 0.f, b1 = 0.f;
                if (MODE == 2) { b0 = bias[col]; b1 = bias[col + 1]; }
                int r0 = m0 + wm + mt * 16 + gid;
                float2 lo = make_float2(acc[mt][nt][0] + b0, acc[mt][nt][1] + b1);
                float2 hi = make_float2(acc[mt][nt][2] + b0, acc[mt][nt][3] + b1);
                *(float2*)&C[(size_t)r0 * LDC + col]       = lo;
                *(float2*)&C[(size_t)(r0 + 8) * LDC + col] = hi;
            }
        }
    }
}

template<int MODE>
__global__ void __launch_bounds__(256, 2) gemm_tf32(
    const float* __restrict__ Bmat,
    const int*   __restrict__ captions,
    const float* __restrict__ W_embed,
    const float* __restrict__ bias)
{
    __shared__ unsigned As[128][36];
    __shared__ unsigned Bs[32][72];
    gemm_body<MODE>(blockIdx.x, blockIdx.y, Bmat, captions, W_embed, bias, As, Bs);
}

// ---------------- attention body: w = softmax(h.A/sqrt(H)); attnP = sum_l w_l P[n,l,:] ----------------
__device__ __forceinline__ void attn_body(int n, float* ph, float* scbuf) {
    float* sc  = scbuf;
    float* wsm = scbuf + 16;
    int t = threadIdx.x;

    #pragma unroll
    for (int i = 0; i < 4; i++) ph[t + 256 * i] = g_h[(size_t)n * Hh + t + 256 * i];
    __syncthreads();

    int warp = t >> 5, lane = t & 31;
    #pragma unroll
    for (int li = 0; li < 2; li++) {
        int l = warp + 8 * li;
        const float* Arow = g_A + (size_t)n * 16 * Hh + (size_t)l * Hh;
        float s = 0.f;
        for (int h = lane; h < Hh; h += 32) s += ph[h] * Arow[h];
        #pragma unroll
        for (int o = 16; o > 0; o >>= 1) s += __shfl_xor_sync(0xffffffff, s, o);
        if (lane == 0) sc[l] = s;
    }
    __syncthreads();

    if (t < 32) {
        float v = (t < 16) ? sc[t] * 0.03125f : -1e30f;   // 1/sqrt(1024)
        float m = v;
        #pragma unroll
        for (int o = 16; o > 0; o >>= 1) m = fmaxf(m, __shfl_xor_sync(0xffffffff, m, o));
        float e = (t < 16) ? expf(v - m) : 0.f;
        float se = e;
        #pragma unroll
        for (int o = 16; o > 0; o >>= 1) se += __shfl_xor_sync(0xffffffff, se, o);
        if (t < 16) wsm[t] = e / se;
    }
    __syncthreads();

    const float* Pn = g_P + (size_t)n * 16 * Gg;
    float w0 = wsm[0], w1 = wsm[1], w2 = wsm[2], w3 = wsm[3];
    float w4 = wsm[4], w5 = wsm[5], w6 = wsm[6], w7 = wsm[7];
    float w8 = wsm[8], w9 = wsm[9], wa = wsm[10], wb = wsm[11];
    float wc = wsm[12], wd = wsm[13], we = wsm[14], wf = wsm[15];
    for (int c = t; c < Gg; c += 256) {
        float a = w0 * Pn[c]           + w1 * Pn[c + Gg]       + w2 * Pn[c + 2 * Gg]  + w3 * Pn[c + 3 * Gg]
                + w4 * Pn[c + 4 * Gg]  + w5 * Pn[c + 5 * Gg]   + w6 * Pn[c + 6 * Gg]  + w7 * Pn[c + 7 * Gg]
                + w8 * Pn[c + 8 * Gg]  + w9 * Pn[c + 9 * Gg]   + wa * Pn[c + 10 * Gg] + wb * Pn[c + 11 * Gg]
                + wc * Pn[c + 12 * Gg] + wd * Pn[c + 13 * Gg]  + we * Pn[c + 14 * Gg] + wf * Pn[c + 15 * Gg];
        g_attnP[(size_t)n * Gg + c] = a;
    }
}

// ---------------- fused per-step kernel: blocks 0..127 = h@Wh GEMM (split-K=2), 128..255 = attn ----------------
__global__ void __launch_bounds__(256, 2) step_kernel(const float* __restrict__ Wh) {
    __shared__ unsigned As[128][36];
    __shared__ unsigned Bs[32][72];
    if (blockIdx.x < 128) {
        gemm_body<3>(blockIdx.x & 63, blockIdx.x >> 6, Wh, nullptr, nullptr, nullptr, As, Bs);
    } else {
        attn_body(blockIdx.x - 128, (float*)&As[0][0], (float*)&Bs[0][0]);
    }
}

// ---------------- gates: z = z0+z1+xw+attnP+b; LSTM update; store h into hn[t] ----------------
__device__ __forceinline__ float4 f4add5(float4 a, float4 b, float4 c, float4 d, float4 e) {
    return make_float4(a.x + b.x + c.x + d.x + e.x,
                       a.y + b.y + c.y + d.y + e.y,
                       a.z + b.z + c.z + d.z + e.z,
                       a.w + b.w + c.w + d.w + e.w);
}
__device__ __forceinline__ void lstm1(float zi, float zf, float zo, float zg,
                                      float cin, float& cout, float& hout) {
    float si = 1.f / (1.f + expf(-zi));
    float sf = 1.f / (1.f + expf(-zf));
    float so = 1.f / (1.f + expf(-zo));
    float gg = tanhf(zg);
    cout = sf * cin + si * gg;
    hout = so * tanhf(cout);
}

__global__ void gates_kernel(const float* __restrict__ b, int t) {
    int q = blockIdx.x * blockDim.x + threadIdx.x;     // handles 4 h-elements
    if (q >= (Nn * Hh) / 4) return;
    int idx = q * 4;                  // n*H + h
    int n  = idx >> 10;
    int h4 = (idx & (Hh - 1)) >> 2;   // float4 index within gate row

    const float4* z0 = (const float4*)(g_zs + (size_t)n * Gg);
    const float4* z1 = (const float4*)(g_zs + (size_t)(Nn + n) * Gg);
    const float4* xw = (const float4*)(g_xw + ((size_t)t * Nn + n) * Gg);
    const float4* ap = (const float4*)(g_attnP + (size_t)n * Gg);
    const float4* b4 = (const float4*)b;

    float4 zi = f4add5(z0[h4],       z1[h4],       xw[h4],       ap[h4],       b4[h4]);
    float4 zf = f4add5(z0[h4 + 256], z1[h4 + 256], xw[h4 + 256], ap[h4 + 256], b4[h4 + 256]);
    float4 zo = f4add5(z0[h4 + 512], z1[h4 + 512], xw[h4 + 512], ap[h4 + 512], b4[h4 + 512]);
    float4 zg = f4add5(z0[h4 + 768], z1[h4 + 768], xw[h4 + 768], ap[h4 + 768], b4[h4 + 768]);

    float4 cin = ((const float4*)g_c)[q];
    float4 co, ho;
    lstm1(zi.x, zf.x, zo.x, zg.x, cin.x, co.x, ho.x);
    lstm1(zi.y, zf.y, zo.y, zg.y, cin.y, co.y, ho.y);
    lstm1(zi.z, zf.z, zo.z, zg.z, cin.z, co.z, ho.z);
    lstm1(zi.w, zf.w, zo.w, zg.w, cin.w, co.w, ho.w);

    ((float4*)g_c)[q] = co;
    ((float4*)g_h)[q] = ho;
    ((float4*)(g_hn + (size_t)t * Nn * Hh))[q] = ho;
}

// ---------------- per-row log-softmax NLL (masked) ----------------
__global__ void loss_kernel(const int* __restrict__ captions) {
    int r = blockIdx.x;            // r = t*128 + n
    int t = r >> 7, n = r & 127;
    int target = captions[n * TCAP + t + 1];
    const float* s = g_scores + (size_t)r * Vv;
    __shared__ float red[256];
    int tid = threadIdx.x;

    // Vv = 10000 = 2500 float4s
    const float4* s4 = (const float4*)s;
    float m = -1e30f;
    for (int v = tid; v < 2500; v += 256) {
        float4 q = s4[v];
        m = fmaxf(m, fmaxf(fmaxf(q.x, q.y), fmaxf(q.z, q.w)));
    }
    red[tid] = m; __syncthreads();
    for (int o = 128; o > 0; o >>= 1) {
        if (tid < o) red[tid] = fmaxf(red[tid], red[tid + o]);
        __syncthreads();
    }
    float mx = red[0];
    __syncthreads();

    float se = 0.f;
    for (int v = tid; v < 2500; v += 256) {
        float4 q = s4[v];
        se += expf(q.x - mx) + expf(q.y - mx) + expf(q.z - mx) + expf(q.w - mx);
    }
    red[tid] = se; __syncthreads();
    for (int o = 128; o > 0; o >>= 1) {
        if (tid < o) red[tid] += red[tid + o];
        __syncthreads();
    }
    if (tid == 0) {
        float lse = logf(red[0]) + mx;
        float nll = lse - s[target];
        g_nll[r] = (target != 0) ? nll : 0.f;
    }
}

// ---------------- deterministic final reduction ----------------
__global__ void finalize_kernel(float* out) {
    __shared__ float red[256];
    int tid = threadIdx.x;
    float s = 0.f;
    for (int i = tid; i < Tt * Nn; i += 256) s += g_nll[i];
    red[tid] = s; __syncthreads();
    for (int o = 128; o > 0; o >>= 1) {
        if (tid < o) red[tid] += red[tid + o];
        __syncthreads();
    }
    if (tid == 0) out[0] = red[0] * (1.0f / (float)Nn);
}

// ---------------- launch ----------------
extern "C" void kernel_launch(void* const* d_in, const int* in_sizes, int n_in,
                              void* d_out, int out_size) {
    const float* features = (const float*)d_in[0];
    const int*   captions = (const int*)  d_in[1];
    const float* W_embed  = (const float*)d_in[2];
    const float* W_proj   = (const float*)d_in[3];
    const float* b_proj   = (const float*)d_in[4];
    const float* Wx       = (const float*)d_in[5];
    const float* Wh       = (const float*)d_in[6];
    const float* Wattn    = (const float*)d_in[7];
    const float* b        = (const float*)d_in[8];
    const float* W_vocab  = (const float*)d_in[9];
    const float* b_vocab  = (const float*)d_in[10];
    float* out = (float*)d_out;

    proj_kernel<<<dim3(8, 128), 256>>>(features, W_proj, b_proj);
    h0_kernel<<<512, 256>>>();

    // precompute x@Wx for all steps (rows t*128+n) and P = A_flat@Wattn (rows n*16+l)
    gemm_tf32<0><<<dim3(64, 32), 256>>>(Wx,    captions, W_embed, nullptr);
    gemm_tf32<1><<<dim3(64, 16), 256>>>(Wattn, captions, W_embed, nullptr);

    for (int t = 0; t < Tt; t++) {
        step_kernel<<<256, 256>>>(Wh);          // attn + h@Wh (split-K=2), concurrent block roles
        gates_kernel<<<128, 256>>>(b, t);
    }

    gemm_tf32<2><<<dim3(157, 32), 256>>>(W_vocab, captions, W_embed, b_vocab);
    loss_kernel<<<Tt * Nn, 256>>>(captions);
    finalize_kernel<<<1, 256>>>(out);
}